// round 12
// baseline (speedup 1.0000x reference)
#include <cuda_runtime.h>
#include <cuda_bf16.h>

// Problem: B=128, T=512, E=8, H=2, dk=4. N = B*T = 65536 rows.
#define TT 512

typedef unsigned long long u64;

// ---- f32x2 packed helpers ----------
__device__ __forceinline__ u64 pack2(float lo, float hi) {
    u64 r; asm("mov.b64 %0, {%1, %2};" : "=l"(r) : "f"(lo), "f"(hi)); return r;
}
__device__ __forceinline__ void unpack2(u64 v, float& lo, float& hi) {
    asm("mov.b64 {%0, %1}, %2;" : "=f"(lo), "=f"(hi) : "l"(v));
}
__device__ __forceinline__ u64 mul2(u64 a, u64 b) {
    u64 r; asm("mul.rn.f32x2 %0, %1, %2;" : "=l"(r) : "l"(a), "l"(b)); return r;
}
__device__ __forceinline__ u64 fma2(u64 a, u64 b, u64 c) {
    u64 r; asm("fma.rn.f32x2 %0, %1, %2, %3;" : "=l"(r) : "l"(a), "l"(b), "l"(c)); return r;
}
__device__ __forceinline__ u64 add2(u64 a, u64 b) {
    u64 r; asm("add.rn.f32x2 %0, %1, %2;" : "=l"(r) : "l"(a), "l"(b)); return r;
}
__device__ __forceinline__ float ex2(float x) {
    float r; asm("ex2.approx.ftz.f32 %0, %1;" : "=f"(r) : "f"(x)); return r;
}

// qlayer closed form: given c[w]=cos(alpha_w):
// out[0]=c1*...*c7 ; out[w>=1]=c0*...*cw
__device__ __forceinline__ void qlayer_from_cos(const float c[8], float o[8]) {
    float t = c[1] * c[2];
    t *= c[3]; t *= c[4]; t *= c[5]; t *= c[6]; t *= c[7];
    o[0] = t;
    float p = c[0] * c[1];
    o[1] = p;
    p *= c[2]; o[2] = p;
    p *= c[3]; o[3] = p;
    p *= c[4]; o[4] = p;
    p *= c[5]; o[5] = p;
    p *= c[6]; o[6] = p;
    p *= c[7]; o[7] = p;
}

struct SmemConsts {
    float Win[64], Wout[64];
    float bin[8], bout[8], l1w[8], l1b[8], l2w[8], l2b[8], tha[8], thf[8];
};

// Full per-row epilogue: ctx -> output row. noinline so its register
// pressure does not inflate the mainloop allocation.
__device__ __noinline__ void epilogue_row(
    const float* __restrict__ ctx, const float* __restrict__ xr,
    float* __restrict__ orow, const SmemConsts& C
) {
    float xv[8];
    {
        float4 e = *reinterpret_cast<const float4*>(xr);
        float4 f = *reinterpret_cast<const float4*>(xr + 4);
        xv[0]=e.x; xv[1]=e.y; xv[2]=e.z; xv[3]=e.w;
        xv[4]=f.x; xv[5]=f.y; xv[6]=f.z; xv[7]=f.w;
    }
    float c[8];
#pragma unroll
    for (int w = 0; w < 8; w++) c[w] = __cosf(ctx[w] + C.tha[w]);
    float ao[8];
    qlayer_from_cos(c, ao);

    float s[8], x1[8];
    float m = 0.0f;
#pragma unroll
    for (int w = 0; w < 8; w++) { s[w] = ao[w] + xv[w]; m += s[w]; }
    m *= 0.125f;
    float v = 0.0f;
#pragma unroll
    for (int w = 0; w < 8; w++) { float d = s[w] - m; v += d * d; }
    v *= 0.125f;
    float istd = rsqrtf(v + 1e-5f);
#pragma unroll
    for (int w = 0; w < 8; w++) x1[w] = (s[w] - m) * istd * C.l1w[w] + C.l1b[w];

    float hq[8];
#pragma unroll
    for (int i = 0; i < 8; i++) {
        float acc = C.bin[i];
#pragma unroll
        for (int j = 0; j < 8; j++) acc += x1[j] * C.Win[i * 8 + j];
        hq[i] = acc;
    }

    // ffn qlayer, wires [0,1,2,2,4,5,6,7]
    float cf[8];
    cf[0] = __cosf(hq[0] + C.thf[0]);
    cf[1] = __cosf(hq[1] + C.thf[1]);
    cf[2] = __cosf(hq[2] + hq[3] + C.thf[2]);
    cf[3] = __cosf(C.thf[3]);
    cf[4] = __cosf(hq[4] + C.thf[4]);
    cf[5] = __cosf(hq[5] + C.thf[5]);
    cf[6] = __cosf(hq[6] + C.thf[6]);
    cf[7] = __cosf(hq[7] + C.thf[7]);
    float qf[8];
    qlayer_from_cos(cf, qf);

    float s2[8];
    float m2 = 0.0f;
#pragma unroll
    for (int i = 0; i < 8; i++) {
        float acc = C.bout[i];
#pragma unroll
        for (int j = 0; j < 8; j++) acc += qf[j] * C.Wout[i * 8 + j];
        s2[i] = acc + x1[i];
        m2 += s2[i];
    }
    m2 *= 0.125f;
    float v2 = 0.0f;
#pragma unroll
    for (int i = 0; i < 8; i++) { float d = s2[i] - m2; v2 += d * d; }
    v2 *= 0.125f;
    float istd2 = rsqrtf(v2 + 1e-5f);

    float res[8];
#pragma unroll
    for (int i = 0; i < 8; i++)
        res[i] = (s2[i] - m2) * istd2 * C.l2w[i] + C.l2b[i];

    *reinterpret_cast<float4*>(orow)     = make_float4(res[0], res[1], res[2], res[3]);
    *reinterpret_cast<float4*>(orow + 4) = make_float4(res[4], res[5], res[6], res[7]);
}

// ---------------------------------------------------------------------------
// Fully fused kernel. grid = 1024 (128 batches x 8 chunks of 64 queries),
// block = 128 threads = 4 warps.
//   Warps 0-1: key-split 0 (keys [0,256));  warps 2-3: key-split 1 ([256,512)).
//   Lane owns ONE query: qi = chunk*64 + (tid & 63). Both heads ride the
//   f32x2 lanes (lo = head0, hi = head1). Warp-uniform key reads -> broadcast.
// Round-12 change: SOFTWARE PREFETCH. Keys for iteration k are loaded one
// iteration ahead into "next" registers, so the 29-cyc LDS latency overlaps
// the ~28-instr compute body of the SAME warp instead of stalling it.
// Register budget raised to 102 (launch_bounds(128,5)) for the extra 16-reg
// key double-buffer; verified spill-free at 95 regs in round 8.
// ---------------------------------------------------------------------------
__global__ __launch_bounds__(128, 5) void fused_kernel(
    const float* __restrict__ x,
    const float* __restrict__ thetas_attn,
    const float* __restrict__ thetas_ffn,
    const float* __restrict__ W_in,
    const float* __restrict__ b_in,
    const float* __restrict__ W_out,
    const float* __restrict__ b_out,
    const float* __restrict__ ln1w, const float* __restrict__ ln1b,
    const float* __restrict__ ln2w, const float* __restrict__ ln2b,
    float* __restrict__ out
) {
    __shared__ ulonglong2 Kpk[TT][2];   // 16 KB lane-packed keys (h0_d, h1_d)
    __shared__ u64 part[5][64];         // 2.5 KB split-1 partials
    __shared__ SmemConsts C;

    const int tid   = threadIdx.x;
    const int b     = blockIdx.x >> 3;
    const int chunk = blockIdx.x & 7;

    if (tid < 64) { C.Win[tid] = W_in[tid]; C.Wout[tid] = W_out[tid]; }
    else if (tid < 72) {
        int i = tid - 64;
        C.bin[i] = b_in[i];  C.bout[i] = b_out[i];
        C.l1w[i] = ln1w[i];  C.l1b[i] = ln1b[i];
        C.l2w[i] = ln2w[i];  C.l2b[i] = ln2b[i];
        C.tha[i] = thetas_attn[i]; C.thf[i] = thetas_ffn[i];
    }

    float th[8];
#pragma unroll
    for (int w = 0; w < 8; w++) th[w] = thetas_attn[w];

    // Prologue: build all 512 keys (both heads) for this batch.
#pragma unroll
    for (int rr = 0; rr < TT / 128; rr++) {
        int i = tid + rr * 128;
        const float* xr = x + ((size_t)(b * TT + i)) * 8;
        float4 xa = *reinterpret_cast<const float4*>(xr);
        float4 xb = *reinterpret_cast<const float4*>(xr + 4);
        float c[8];
        c[0] = __cosf(xa.x + th[0]);
        c[1] = __cosf(xa.y + th[1]);
        c[2] = __cosf(xa.z + th[2]);
        c[3] = __cosf(xa.w + th[3]);
        c[4] = __cosf(xb.x + th[4]);
        c[5] = __cosf(xb.y + th[5]);
        c[6] = __cosf(xb.z + th[6]);
        c[7] = __cosf(xb.w + th[7]);
        float o[8];
        qlayer_from_cos(c, o);
        ulonglong2 p0, p1;
        p0.x = pack2(o[0], o[4]);
        p0.y = pack2(o[1], o[5]);
        p1.x = pack2(o[2], o[6]);
        p1.y = pack2(o[3], o[7]);
        Kpk[i][0] = p0;
        Kpk[i][1] = p1;
    }
    __syncthreads();

    const int split = tid >> 6;            // warps 0-1 -> 0, warps 2-3 -> 1
    const int qloc  = tid & 63;            // query within chunk
    const int qi    = chunk * 64 + qloc;

    // Query pre-scaled by 0.5*log2(e) (softmax scale 1/sqrt(dk)=0.5 folded).
    const float SC = 0.72134752044f;
    const u64 SC2 = pack2(SC, SC);
    ulonglong2 qa = Kpk[qi][0], qb = Kpk[qi][1];
    u64 qp0 = mul2(qa.x, SC2), qp1 = mul2(qa.y, SC2);
    u64 qp2 = mul2(qb.x, SC2), qp3 = mul2(qb.y, SC2);

    u64 acc0 = 0, acc1 = 0, acc2 = 0, acc3 = 0;
    u64 dn0 = 0, dn1 = 0;

    const int k0   = split * (TT / 2);
    const int kend = k0 + TT / 2;

    // Preload first key pair.
    ulonglong2 kaX = Kpk[k0][0],     kbX = Kpk[k0][1];
    ulonglong2 kaY = Kpk[k0 + 1][0], kbY = Kpk[k0 + 1][1];

    // |exp2 arg| <= 4*0.72 < 3 : no max subtraction needed.
#pragma unroll 1
    for (int k = k0; k < kend; k += 2) {
        // Prefetch next pair (clamped; address warp-uniform -> broadcast).
        int kn = (k + 2 < kend) ? (k + 2) : k0;
        ulonglong2 naX = Kpk[kn][0],     nbX = Kpk[kn][1];
        ulonglong2 naY = Kpk[kn + 1][0], nbY = Kpk[kn + 1][1];

        // Compute on current pair while the prefetch is in flight.
        u64 sX = mul2(qp0, kaX.x);
        u64 sY = mul2(qp0, kaY.x);
        sX = fma2(qp1, kaX.y, sX);
        sY = fma2(qp1, kaY.y, sY);
        sX = fma2(qp2, kbX.x, sX);
        sY = fma2(qp2, kbY.x, sY);
        sX = fma2(qp3, kbX.y, sX);
        sY = fma2(qp3, kbY.y, sY);

        float x0, x1f, y0, y1;
        unpack2(sX, x0, x1f);
        unpack2(sY, y0, y1);
        u64 eX = pack2(ex2(x0), ex2(x1f));
        u64 eY = pack2(ex2(y0), ex2(y1));

        acc0 = fma2(eX, kaX.x, acc0);
        acc1 = fma2(eX, kaX.y, acc1);
        acc2 = fma2(eX, kbX.x, acc2);
        acc3 = fma2(eX, kbX.y, acc3);
        dn0  = add2(dn0, eX);
        acc0 = fma2(eY, kaY.x, acc0);
        acc1 = fma2(eY, kaY.y, acc1);
        acc2 = fma2(eY, kbY.x, acc2);
        acc3 = fma2(eY, kbY.y, acc3);
        dn1  = add2(dn1, eY);

        // Rotate.
        kaX = naX; kbX = nbX; kaY = naY; kbY = nbY;
    }
    u64 dn = add2(dn0, dn1);

    // Split 1 publishes partials; split 0 combines.
    if (split == 1) {
        part[0][qloc] = acc0;
        part[1][qloc] = acc1;
        part[2][qloc] = acc2;
        part[3][qloc] = acc3;
        part[4][qloc] = dn;
    }
    __syncthreads();

    if (split == 0) {
        acc0 = add2(acc0, part[0][qloc]);
        acc1 = add2(acc1, part[1][qloc]);
        acc2 = add2(acc2, part[2][qloc]);
        acc3 = add2(acc3, part[3][qloc]);
        dn   = add2(dn,   part[4][qloc]);

        float d0, d1; unpack2(dn, d0, d1);
        float inv0 = __fdividef(1.0f, d0);
        float inv1 = __fdividef(1.0f, d1);
        float ctx[8], lo, hi;
        unpack2(acc0, lo, hi); ctx[0] = lo * inv0; ctx[4] = hi * inv1;
        unpack2(acc1, lo, hi); ctx[1] = lo * inv0; ctx[5] = hi * inv1;
        unpack2(acc2, lo, hi); ctx[2] = lo * inv0; ctx[6] = hi * inv1;
        unpack2(acc3, lo, hi); ctx[3] = lo * inv0; ctx[7] = hi * inv1;

        size_t row = (size_t)(b * TT + qi);
        epilogue_row(ctx, x + row * 8, out + row * 8, C);
    }
}

extern "C" void kernel_launch(void* const* d_in, const int* in_sizes, int n_in,
                              void* d_out, int out_size) {
    const float* x           = (const float*)d_in[0];
    const float* thetas_attn = (const float*)d_in[1];
    const float* thetas_ffn  = (const float*)d_in[2];
    const float* W_in        = (const float*)d_in[3];
    const float* b_in        = (const float*)d_in[4];
    const float* W_out       = (const float*)d_in[5];
    const float* b_out       = (const float*)d_in[6];
    const float* ln1w        = (const float*)d_in[7];
    const float* ln1b        = (const float*)d_in[8];
    const float* ln2w        = (const float*)d_in[9];
    const float* ln2b        = (const float*)d_in[10];
    float* out = (float*)d_out;

    fused_kernel<<<128 * 8, 128>>>(x, thetas_attn, thetas_ffn,
                                   W_in, b_in, W_out, b_out,
                                   ln1w, ln1b, ln2w, ln2b, out);
}

// round 13
// speedup vs baseline: 1.1760x; 1.1760x over previous
#include <cuda_runtime.h>
#include <cuda_bf16.h>

// Problem: B=128, T=512, E=8, H=2, dk=4. N = B*T = 65536 rows.
#define TT 512

typedef unsigned long long u64;

// ---- f32x2 packed helpers ----------
__device__ __forceinline__ u64 pack2(float lo, float hi) {
    u64 r; asm("mov.b64 %0, {%1, %2};" : "=l"(r) : "f"(lo), "f"(hi)); return r;
}
__device__ __forceinline__ void unpack2(u64 v, float& lo, float& hi) {
    asm("mov.b64 {%0, %1}, %2;" : "=f"(lo), "=f"(hi) : "l"(v));
}
__device__ __forceinline__ u64 mul2(u64 a, u64 b) {
    u64 r; asm("mul.rn.f32x2 %0, %1, %2;" : "=l"(r) : "l"(a), "l"(b)); return r;
}
__device__ __forceinline__ u64 fma2(u64 a, u64 b, u64 c) {
    u64 r; asm("fma.rn.f32x2 %0, %1, %2, %3;" : "=l"(r) : "l"(a), "l"(b), "l"(c)); return r;
}
__device__ __forceinline__ u64 add2(u64 a, u64 b) {
    u64 r; asm("add.rn.f32x2 %0, %1, %2;" : "=l"(r) : "l"(a), "l"(b)); return r;
}
__device__ __forceinline__ float ex2(float x) {
    float r; asm("ex2.approx.ftz.f32 %0, %1;" : "=f"(r) : "f"(x)); return r;
}

// qlayer closed form: given c[w]=cos(alpha_w):
// out[0]=c1*...*c7 ; out[w>=1]=c0*...*cw
__device__ __forceinline__ void qlayer_from_cos(const float c[8], float o[8]) {
    float t = c[1] * c[2];
    t *= c[3]; t *= c[4]; t *= c[5]; t *= c[6]; t *= c[7];
    o[0] = t;
    float p = c[0] * c[1];
    o[1] = p;
    p *= c[2]; o[2] = p;
    p *= c[3]; o[3] = p;
    p *= c[4]; o[4] = p;
    p *= c[5]; o[5] = p;
    p *= c[6]; o[6] = p;
    p *= c[7]; o[7] = p;
}

struct SmemConsts {
    float Win[64], Wout[64];
    float bin[8], bout[8], l1w[8], l1b[8], l2w[8], l2b[8], tha[8], thf[8];
};

// Full per-row epilogue: ctx -> output row. noinline so its register
// pressure does not inflate the mainloop allocation.
__device__ __noinline__ void epilogue_row(
    const float* __restrict__ ctx, const float* __restrict__ xr,
    float* __restrict__ orow, const SmemConsts& C
) {
    float xv[8];
    {
        float4 e = *reinterpret_cast<const float4*>(xr);
        float4 f = *reinterpret_cast<const float4*>(xr + 4);
        xv[0]=e.x; xv[1]=e.y; xv[2]=e.z; xv[3]=e.w;
        xv[4]=f.x; xv[5]=f.y; xv[6]=f.z; xv[7]=f.w;
    }
    float c[8];
#pragma unroll
    for (int w = 0; w < 8; w++) c[w] = __cosf(ctx[w] + C.tha[w]);
    float ao[8];
    qlayer_from_cos(c, ao);

    float s[8], x1[8];
    float m = 0.0f;
#pragma unroll
    for (int w = 0; w < 8; w++) { s[w] = ao[w] + xv[w]; m += s[w]; }
    m *= 0.125f;
    float v = 0.0f;
#pragma unroll
    for (int w = 0; w < 8; w++) { float d = s[w] - m; v += d * d; }
    v *= 0.125f;
    float istd = rsqrtf(v + 1e-5f);
#pragma unroll
    for (int w = 0; w < 8; w++) x1[w] = (s[w] - m) * istd * C.l1w[w] + C.l1b[w];

    float hq[8];
#pragma unroll
    for (int i = 0; i < 8; i++) {
        float acc = C.bin[i];
#pragma unroll
        for (int j = 0; j < 8; j++) acc += x1[j] * C.Win[i * 8 + j];
        hq[i] = acc;
    }

    // ffn qlayer, wires [0,1,2,2,4,5,6,7]
    float cf[8];
    cf[0] = __cosf(hq[0] + C.thf[0]);
    cf[1] = __cosf(hq[1] + C.thf[1]);
    cf[2] = __cosf(hq[2] + hq[3] + C.thf[2]);
    cf[3] = __cosf(C.thf[3]);
    cf[4] = __cosf(hq[4] + C.thf[4]);
    cf[5] = __cosf(hq[5] + C.thf[5]);
    cf[6] = __cosf(hq[6] + C.thf[6]);
    cf[7] = __cosf(hq[7] + C.thf[7]);
    float qf[8];
    qlayer_from_cos(cf, qf);

    float s2[8];
    float m2 = 0.0f;
#pragma unroll
    for (int i = 0; i < 8; i++) {
        float acc = C.bout[i];
#pragma unroll
        for (int j = 0; j < 8; j++) acc += qf[j] * C.Wout[i * 8 + j];
        s2[i] = acc + x1[i];
        m2 += s2[i];
    }
    m2 *= 0.125f;
    float v2 = 0.0f;
#pragma unroll
    for (int i = 0; i < 8; i++) { float d = s2[i] - m2; v2 += d * d; }
    v2 *= 0.125f;
    float istd2 = rsqrtf(v2 + 1e-5f);

    float res[8];
#pragma unroll
    for (int i = 0; i < 8; i++)
        res[i] = (s2[i] - m2) * istd2 * C.l2w[i] + C.l2b[i];

    *reinterpret_cast<float4*>(orow)     = make_float4(res[0], res[1], res[2], res[3]);
    *reinterpret_cast<float4*>(orow + 4) = make_float4(res[4], res[5], res[6], res[7]);
}

// ---------------------------------------------------------------------------
// Fully fused kernel. grid = 1024 (128 batches x 8 chunks of 64 queries),
// block = 128 threads = 4 warps.
//   Warps 0-1: key-split 0 (keys [0,256));  warps 2-3: key-split 1 ([256,512)).
//   Lane owns ONE query: qi = chunk*64 + (tid & 63). Both heads ride the
//   f32x2 lanes (lo = head0, hi = head1). Warp-uniform key reads -> broadcast.
// Round-13 change: MOV-free ping-pong prefetch. 4 keys per iteration, two
// named buffer sets; each set is reloaded DIRECTLY from smem (no rotate
// MOVs), pointer+immediate addressing (one IADD/iter), and a 2-key zero pad
// on Kpk removes the tail clamp entirely. This keeps round-12's latency
// hiding (issue 60%) without its 42% alu-pipe overhead.
// ---------------------------------------------------------------------------
__global__ __launch_bounds__(128, 6) void fused_kernel(
    const float* __restrict__ x,
    const float* __restrict__ thetas_attn,
    const float* __restrict__ thetas_ffn,
    const float* __restrict__ W_in,
    const float* __restrict__ b_in,
    const float* __restrict__ W_out,
    const float* __restrict__ b_out,
    const float* __restrict__ ln1w, const float* __restrict__ ln1b,
    const float* __restrict__ ln2w, const float* __restrict__ ln2b,
    float* __restrict__ out
) {
    __shared__ ulonglong2 Kpk[TT + 2][2];   // +2 pad keys: tail prefetch target
    __shared__ u64 part[5][64];             // split-1 partials
    __shared__ SmemConsts C;

    const int tid   = threadIdx.x;
    const int b     = blockIdx.x >> 3;
    const int chunk = blockIdx.x & 7;

    if (tid < 64) { C.Win[tid] = W_in[tid]; C.Wout[tid] = W_out[tid]; }
    else if (tid < 72) {
        int i = tid - 64;
        C.bin[i] = b_in[i];  C.bout[i] = b_out[i];
        C.l1w[i] = ln1w[i];  C.l1b[i] = ln1b[i];
        C.l2w[i] = ln2w[i];  C.l2b[i] = ln2b[i];
        C.tha[i] = thetas_attn[i]; C.thf[i] = thetas_ffn[i];
    }
    if (tid < 2) {   // zero the pad keys
        Kpk[TT + tid][0] = make_ulonglong2(0, 0);
        Kpk[TT + tid][1] = make_ulonglong2(0, 0);
    }

    float th[8];
#pragma unroll
    for (int w = 0; w < 8; w++) th[w] = thetas_attn[w];

    // Prologue: build all 512 keys (both heads) for this batch.
#pragma unroll
    for (int rr = 0; rr < TT / 128; rr++) {
        int i = tid + rr * 128;
        const float* xr = x + ((size_t)(b * TT + i)) * 8;
        float4 xa = *reinterpret_cast<const float4*>(xr);
        float4 xb = *reinterpret_cast<const float4*>(xr + 4);
        float c[8];
        c[0] = __cosf(xa.x + th[0]);
        c[1] = __cosf(xa.y + th[1]);
        c[2] = __cosf(xa.z + th[2]);
        c[3] = __cosf(xa.w + th[3]);
        c[4] = __cosf(xb.x + th[4]);
        c[5] = __cosf(xb.y + th[5]);
        c[6] = __cosf(xb.z + th[6]);
        c[7] = __cosf(xb.w + th[7]);
        float o[8];
        qlayer_from_cos(c, o);
        ulonglong2 p0, p1;
        p0.x = pack2(o[0], o[4]);
        p0.y = pack2(o[1], o[5]);
        p1.x = pack2(o[2], o[6]);
        p1.y = pack2(o[3], o[7]);
        Kpk[i][0] = p0;
        Kpk[i][1] = p1;
    }
    __syncthreads();

    const int split = tid >> 6;            // warps 0-1 -> 0, warps 2-3 -> 1
    const int qloc  = tid & 63;            // query within chunk
    const int qi    = chunk * 64 + qloc;

    // Query pre-scaled by 0.5*log2(e) (softmax scale 1/sqrt(dk)=0.5 folded).
    const float SC = 0.72134752044f;
    const u64 SC2 = pack2(SC, SC);
    ulonglong2 qa = Kpk[qi][0], qb = Kpk[qi][1];
    u64 qp0 = mul2(qa.x, SC2), qp1 = mul2(qa.y, SC2);
    u64 qp2 = mul2(qb.x, SC2), qp3 = mul2(qb.y, SC2);

    u64 acc0 = 0, acc1 = 0, acc2 = 0, acc3 = 0;
    u64 dn0 = 0, dn1 = 0;

    const int k0 = split * (TT / 2);
    // Flat pointer over Kpk entries (2 ulonglong2 per key, warp-uniform).
    const ulonglong2* kp = &Kpk[k0][0];

    // Preload buffer set A with keys k0, k0+1.
    ulonglong2 a0 = kp[0], a1 = kp[1], a2 = kp[2], a3 = kp[3];

    // |exp2 arg| <= 4*0.72 < 3 : no max subtraction needed.
    // 4 keys/iter; set B loaded at top, set A reloaded mid-body (prefetch).
#pragma unroll 1
    for (int it = 0; it < (TT / 2) / 4; it++) {
        // Load set B: keys +2, +3.
        ulonglong2 b0k = kp[4], b1k = kp[5], b2k = kp[6], b3k = kp[7];

        // ---- compute set A (keys +0, +1) ----
        u64 sX = mul2(qp0, a0.x);
        u64 sY = mul2(qp0, a2.x);
        sX = fma2(qp1, a0.y, sX);
        sY = fma2(qp1, a2.y, sY);
        sX = fma2(qp2, a1.x, sX);
        sY = fma2(qp2, a3.x, sY);
        sX = fma2(qp3, a1.y, sX);
        sY = fma2(qp3, a3.y, sY);
        float x0, x1f, y0, y1;
        unpack2(sX, x0, x1f);
        unpack2(sY, y0, y1);
        u64 eX = pack2(ex2(x0), ex2(x1f));
        u64 eY = pack2(ex2(y0), ex2(y1));
        acc0 = fma2(eX, a0.x, acc0);
        acc1 = fma2(eX, a0.y, acc1);
        acc2 = fma2(eX, a1.x, acc2);
        acc3 = fma2(eX, a1.y, acc3);
        dn0  = add2(dn0, eX);
        acc0 = fma2(eY, a2.x, acc0);
        acc1 = fma2(eY, a2.y, acc1);
        acc2 = fma2(eY, a3.x, acc2);
        acc3 = fma2(eY, a3.y, acc3);
        dn1  = add2(dn1, eY);

        // Reload set A directly with keys +4, +5 (pad covers the tail).
        a0 = kp[8]; a1 = kp[9]; a2 = kp[10]; a3 = kp[11];

        // ---- compute set B (keys +2, +3) ----
        u64 tX = mul2(qp0, b0k.x);
        u64 tY = mul2(qp0, b2k.x);
        tX = fma2(qp1, b0k.y, tX);
        tY = fma2(qp1, b2k.y, tY);
        tX = fma2(qp2, b1k.x, tX);
        tY = fma2(qp2, b3k.x, tY);
        tX = fma2(qp3, b1k.y, tX);
        tY = fma2(qp3, b3k.y, tY);
        float u0, u1, v0, v1;
        unpack2(tX, u0, u1);
        unpack2(tY, v0, v1);
        u64 fX = pack2(ex2(u0), ex2(u1));
        u64 fY = pack2(ex2(v0), ex2(v1));
        acc0 = fma2(fX, b0k.x, acc0);
        acc1 = fma2(fX, b0k.y, acc1);
        acc2 = fma2(fX, b1k.x, acc2);
        acc3 = fma2(fX, b1k.y, acc3);
        dn0  = add2(dn0, fX);
        acc0 = fma2(fY, b2k.x, acc0);
        acc1 = fma2(fY, b2k.y, acc1);
        acc2 = fma2(fY, b3k.x, acc2);
        acc3 = fma2(fY, b3k.y, acc3);
        dn1  = add2(dn1, fY);

        kp += 8;
    }
    u64 dn = add2(dn0, dn1);

    // Split 1 publishes partials; split 0 combines.
    if (split == 1) {
        part[0][qloc] = acc0;
        part[1][qloc] = acc1;
        part[2][qloc] = acc2;
        part[3][qloc] = acc3;
        part[4][qloc] = dn;
    }
    __syncthreads();

    if (split == 0) {
        acc0 = add2(acc0, part[0][qloc]);
        acc1 = add2(acc1, part[1][qloc]);
        acc2 = add2(acc2, part[2][qloc]);
        acc3 = add2(acc3, part[3][qloc]);
        dn   = add2(dn,   part[4][qloc]);

        float d0, d1; unpack2(dn, d0, d1);
        float inv0 = __fdividef(1.0f, d0);
        float inv1 = __fdividef(1.0f, d1);
        float ctx[8], lo, hi;
        unpack2(acc0, lo, hi); ctx[0] = lo * inv0; ctx[4] = hi * inv1;
        unpack2(acc1, lo, hi); ctx[1] = lo * inv0; ctx[5] = hi * inv1;
        unpack2(acc2, lo, hi); ctx[2] = lo * inv0; ctx[6] = hi * inv1;
        unpack2(acc3, lo, hi); ctx[3] = lo * inv0; ctx[7] = hi * inv1;

        size_t row = (size_t)(b * TT + qi);
        epilogue_row(ctx, x + row * 8, out + row * 8, C);
    }
}

extern "C" void kernel_launch(void* const* d_in, const int* in_sizes, int n_in,
                              void* d_out, int out_size) {
    const float* x           = (const float*)d_in[0];
    const float* thetas_attn = (const float*)d_in[1];
    const float* thetas_ffn  = (const float*)d_in[2];
    const float* W_in        = (const float*)d_in[3];
    const float* b_in        = (const float*)d_in[4];
    const float* W_out       = (const float*)d_in[5];
    const float* b_out       = (const float*)d_in[6];
    const float* ln1w        = (const float*)d_in[7];
    const float* ln1b        = (const float*)d_in[8];
    const float* ln2w        = (const float*)d_in[9];
    const float* ln2b        = (const float*)d_in[10];
    float* out = (float*)d_out;

    fused_kernel<<<128 * 8, 128>>>(x, thetas_attn, thetas_ffn,
                                   W_in, b_in, W_out, b_out,
                                   ln1w, ln1b, ln2w, ln2b, out);
}